// round 10
// baseline (speedup 1.0000x reference)
#include <cuda_runtime.h>
#include <math.h>

// Problem constants
#define HH     8192
#define IDIM   4096
#define ODIM   4096
#define NTOT   (HH + ODIM)      // 12288
#define NSTEPS 100

// Scratch (no allocations allowed) — 16B aligned for float4 access.
__device__ __align__(128) float g_Ihid[HH];    // compress(W1 @ v_input)
__device__ __align__(128) float g_Iout[ODIM];  // compress(W2 @ I_hidden)
__device__ __align__(128) float g_total[NTOT]; // [I_hidden - Wfb@I_out ; I_out]

__device__ __forceinline__ float compress_fn(float x, float gain) {
    float s = (x > 0.0f) ? 1.0f : ((x < 0.0f) ? -1.0f : 0.0f);
    return s * log1pf(gain * fabsf(x) + 1e-6f);
}

// Block-wide sum reduce for 256 threads (8 warps). Result valid in thread 0.
__device__ __forceinline__ float block_reduce_256(float val) {
    __shared__ float s[8];
    #pragma unroll
    for (int o = 16; o > 0; o >>= 1)
        val += __shfl_xor_sync(0xffffffffu, val, o);
    if ((threadIdx.x & 31) == 0) s[threadIdx.x >> 5] = val;
    __syncthreads();
    if (threadIdx.x < 32) {
        val = (threadIdx.x < 8) ? s[threadIdx.x] : 0.0f;
        #pragma unroll
        for (int o = 4; o > 0; o >>= 1)
            val += __shfl_xor_sync(0xffffffffu, val, o);
    }
    return val;
}

// One block (256 threads) computes dot(W[row, :], x) with float4 loads.
template <int NCOLS>
__device__ __forceinline__ float row_dot(const float* __restrict__ W,
                                         const float* __restrict__ x) {
    const float4* Wr = reinterpret_cast<const float4*>(W) +
                       (size_t)blockIdx.x * (NCOLS / 4);
    const float4* xv = reinterpret_cast<const float4*>(x);
    constexpr int PER = NCOLS / 4 / 256;
    float acc = 0.0f;
    #pragma unroll
    for (int k = 0; k < PER; ++k) {
        int idx = k * 256 + threadIdx.x;
        float4 w = Wr[idx];
        float4 v = xv[idx];
        acc = fmaf(w.x, v.x, acc);
        acc = fmaf(w.y, v.y, acc);
        acc = fmaf(w.z, v.z, acc);
        acc = fmaf(w.w, v.w, acc);
    }
    return acc;
}

// GEMV 1: g_Ihid = compress(W1 @ v_input, gain1)
__global__ __launch_bounds__(256) void k_gemv1(const float* __restrict__ W1,
                                               const float* __restrict__ vin,
                                               const float* __restrict__ gain1) {
    float acc = row_dot<IDIM>(W1, vin);
    acc = block_reduce_256(acc);
    if (threadIdx.x == 0)
        g_Ihid[blockIdx.x] = compress_fn(acc, gain1[0]);
}

// GEMV 2: g_Iout = compress(W2 @ g_Ihid, gain2); also fill g_total[H..]
__global__ __launch_bounds__(256) void k_gemv2(const float* __restrict__ W2,
                                               const float* __restrict__ gain2) {
    float acc = row_dot<HH>(W2, g_Ihid);
    acc = block_reduce_256(acc);
    if (threadIdx.x == 0) {
        float r = compress_fn(acc, gain2[0]);
        g_Iout[blockIdx.x] = r;
        g_total[HH + blockIdx.x] = r;
    }
}

// GEMV 3: g_total[0..H) = g_Ihid - W_feedback @ g_Iout
__global__ __launch_bounds__(256) void k_gemv3(const float* __restrict__ Wfb) {
    float acc = row_dot<ODIM>(Wfb, g_Iout);
    acc = block_reduce_256(acc);
    if (threadIdx.x == 0)
        g_total[blockIdx.x] = g_Ihid[blockIdx.x] - acc;
}

// Izhikevich dynamics: one thread per neuron, 100 steps.
// Output layout: out[0] = loss (written elsewhere),
//   v_vec at out[1 + t*NTOT + i], u_vec at out[1 + NSTEPS*NTOT + t*NTOT + i].
__global__ __launch_bounds__(256) void k_izhi(float* __restrict__ out) {
    int i = blockIdx.x * 256 + threadIdx.x;
    if (i >= NTOT) return;
    float Iin = g_total[i];
    float* vout = out + 1;
    float* uout = out + 1 + (size_t)NSTEPS * NTOT;

    float v = -65.0f;
    float u = 0.2f * -65.0f;   // B * v0 = -13
    vout[i] = v;
    uout[i] = u;

    #pragma unroll 4
    for (int t = 1; t < NSTEPS; ++t) {
        // v_new = v + DT*(0.04 v^2 + 5 v + 0.14 - u + I),  DT = 1
        float vn = v + (0.04f * v * v + 5.0f * v + 0.14f - u + Iin);
        // u_new = u + DT*A*(B*v_prev - u)
        float un = u + 0.02f * (0.2f * v - u);
        bool spiked = (vn >= 30.0f);
        v = spiked ? -65.0f : vn;
        u = spiked ? (un + 8.0f) : un;
        vout[(size_t)t * NTOT + i] = v;
        uout[(size_t)t * NTOT + i] = u;
    }
}

// loss = mean((I_output - target)^2), single block of 1024 threads.
__global__ __launch_bounds__(1024) void k_loss(const float* __restrict__ target,
                                               float* __restrict__ out) {
    float acc = 0.0f;
    for (int i = threadIdx.x; i < ODIM; i += 1024) {
        float d = g_Iout[i] - target[i];
        acc = fmaf(d, d, acc);
    }
    __shared__ float s[32];
    #pragma unroll
    for (int o = 16; o > 0; o >>= 1)
        acc += __shfl_xor_sync(0xffffffffu, acc, o);
    if ((threadIdx.x & 31) == 0) s[threadIdx.x >> 5] = acc;
    __syncthreads();
    if (threadIdx.x < 32) {
        acc = s[threadIdx.x];
        #pragma unroll
        for (int o = 16; o > 0; o >>= 1)
            acc += __shfl_xor_sync(0xffffffffu, acc, o);
        if (threadIdx.x == 0)
            out[0] = acc / (float)ODIM;
    }
}

extern "C" void kernel_launch(void* const* d_in, const int* in_sizes, int n_in,
                              void* d_out, int out_size) {
    // metadata order: v_input, target_output, W1, W2, W_feedback, gain1, gain2
    const float* v_input = (const float*)d_in[0];
    const float* target  = (const float*)d_in[1];
    const float* W1      = (const float*)d_in[2];
    const float* W2      = (const float*)d_in[3];
    const float* Wfb     = (const float*)d_in[4];
    const float* gain1   = (const float*)d_in[5];
    const float* gain2   = (const float*)d_in[6];
    float* out = (float*)d_out;

    k_gemv1<<<HH, 256>>>(W1, v_input, gain1);
    k_gemv2<<<ODIM, 256>>>(W2, gain2);
    k_gemv3<<<HH, 256>>>(Wfb);
    k_izhi<<<(NTOT + 255) / 256, 256>>>(out);
    k_loss<<<1, 1024>>>(target, out);
    (void)in_sizes; (void)n_in; (void)out_size;
}

// round 11
// speedup vs baseline: 1.0280x; 1.0280x over previous
#include <cuda_runtime.h>
#include <math.h>

// Problem constants
#define HH     8192
#define IDIM   4096
#define ODIM   4096
#define NTOT   (HH + ODIM)      // 12288
#define NSTEPS 100
#define RPB    4                // rows per block

// Scratch (no allocations allowed)
__device__ __align__(128) float g_Ihid[HH];    // compress(W1 @ v_input)
__device__ __align__(128) float g_Iout[ODIM];  // compress(W2 @ I_hidden)

__device__ __forceinline__ float compress_fn(float x, float gain) {
    float s = (x > 0.0f) ? 1.0f : ((x < 0.0f) ? -1.0f : 0.0f);
    return s * log1pf(gain * fabsf(x) + 1e-6f);
}

// 4-row dot product: 256 threads, each thread accumulates its idx-slice for
// 4 consecutive rows. Per-row FMA ordering is IDENTICAL to the 1-row version
// that passed (thread t handles idx = k*256+t, elements in .x .y .z .w order).
template <int NCOLS>
__device__ __forceinline__ void rows4_dot(const float* __restrict__ W,
                                          const float* __restrict__ x,
                                          int row0,
                                          float& a0, float& a1, float& a2, float& a3) {
    const float4* xv = reinterpret_cast<const float4*>(x);
    const float4* w0 = reinterpret_cast<const float4*>(W + (size_t)(row0 + 0) * NCOLS);
    const float4* w1 = reinterpret_cast<const float4*>(W + (size_t)(row0 + 1) * NCOLS);
    const float4* w2 = reinterpret_cast<const float4*>(W + (size_t)(row0 + 2) * NCOLS);
    const float4* w3 = reinterpret_cast<const float4*>(W + (size_t)(row0 + 3) * NCOLS);
    constexpr int PER = NCOLS / 4 / 256;
    a0 = a1 = a2 = a3 = 0.0f;
    #pragma unroll
    for (int k = 0; k < PER; ++k) {
        int idx = k * 256 + threadIdx.x;
        float4 xx = xv[idx];
        float4 r0 = w0[idx];
        float4 r1 = w1[idx];
        float4 r2 = w2[idx];
        float4 r3 = w3[idx];
        a0 = fmaf(r0.x, xx.x, a0); a0 = fmaf(r0.y, xx.y, a0);
        a0 = fmaf(r0.z, xx.z, a0); a0 = fmaf(r0.w, xx.w, a0);
        a1 = fmaf(r1.x, xx.x, a1); a1 = fmaf(r1.y, xx.y, a1);
        a1 = fmaf(r1.z, xx.z, a1); a1 = fmaf(r1.w, xx.w, a1);
        a2 = fmaf(r2.x, xx.x, a2); a2 = fmaf(r2.y, xx.y, a2);
        a2 = fmaf(r2.z, xx.z, a2); a2 = fmaf(r2.w, xx.w, a2);
        a3 = fmaf(r3.x, xx.x, a3); a3 = fmaf(r3.y, xx.y, a3);
        a3 = fmaf(r3.z, xx.z, a3); a3 = fmaf(r3.w, xx.w, a3);
    }
}

// Block reduce of 4 independent sums for 256 threads (8 warps).
// Same xor-shuffle tree per value as the passing kernel. Results in thread 0.
__device__ __forceinline__ void block_reduce4(float& a0, float& a1, float& a2, float& a3) {
    __shared__ float s[8][4];
    #pragma unroll
    for (int o = 16; o > 0; o >>= 1) {
        a0 += __shfl_xor_sync(0xffffffffu, a0, o);
        a1 += __shfl_xor_sync(0xffffffffu, a1, o);
        a2 += __shfl_xor_sync(0xffffffffu, a2, o);
        a3 += __shfl_xor_sync(0xffffffffu, a3, o);
    }
    if ((threadIdx.x & 31) == 0) {
        int w = threadIdx.x >> 5;
        s[w][0] = a0; s[w][1] = a1; s[w][2] = a2; s[w][3] = a3;
    }
    __syncthreads();
    if (threadIdx.x < 32) {
        bool in = threadIdx.x < 8;
        a0 = in ? s[threadIdx.x][0] : 0.0f;
        a1 = in ? s[threadIdx.x][1] : 0.0f;
        a2 = in ? s[threadIdx.x][2] : 0.0f;
        a3 = in ? s[threadIdx.x][3] : 0.0f;
        #pragma unroll
        for (int o = 4; o > 0; o >>= 1) {
            a0 += __shfl_xor_sync(0xffffffffu, a0, o);
            a1 += __shfl_xor_sync(0xffffffffu, a1, o);
            a2 += __shfl_xor_sync(0xffffffffu, a2, o);
            a3 += __shfl_xor_sync(0xffffffffu, a3, o);
        }
    }
}

// Izhikevich trajectory for one neuron: 100 steps, lanes 0-3 of a block run
// 4 consecutive neurons -> 16B-coalesced stores per step.
// Output layout: out[0]=loss, v at out[1 + t*NTOT + n], u after all v.
__device__ __forceinline__ void izhi_run(int n, float Iin, float* __restrict__ out) {
    float* vp = out + 1 + n;
    float* up = out + 1 + (size_t)NSTEPS * NTOT + n;
    float v = -65.0f;
    float u = 0.2f * -65.0f;   // -13
    *vp = v; *up = u;
    #pragma unroll 4
    for (int t = 1; t < NSTEPS; ++t) {
        vp += NTOT; up += NTOT;
        float vn = v + (0.04f * v * v + 5.0f * v + 0.14f - u + Iin);
        float un = u + 0.02f * (0.2f * v - u);
        bool sp = (vn >= 30.0f);
        v = sp ? -65.0f : vn;
        u = sp ? (un + 8.0f) : un;
        *vp = v; *up = u;
    }
}

// GEMV 1: g_Ihid = compress(W1 @ v_input, gain1). Grid = HH/RPB = 2048.
__global__ __launch_bounds__(256) void k_gemv1(const float* __restrict__ W1,
                                               const float* __restrict__ vin,
                                               const float* __restrict__ gain1) {
    int row0 = blockIdx.x * RPB;
    float a0, a1, a2, a3;
    rows4_dot<IDIM>(W1, vin, row0, a0, a1, a2, a3);
    block_reduce4(a0, a1, a2, a3);
    if (threadIdx.x == 0) {
        float g = gain1[0];
        g_Ihid[row0 + 0] = compress_fn(a0, g);
        g_Ihid[row0 + 1] = compress_fn(a1, g);
        g_Ihid[row0 + 2] = compress_fn(a2, g);
        g_Ihid[row0 + 3] = compress_fn(a3, g);
    }
}

// GEMV 2: g_Iout = compress(W2 @ g_Ihid, gain2), then lanes 0-3 run the
// Izhikevich scan for the 4 output neurons of this block (they depend only
// on I_output). Grid = ODIM/RPB = 1024.
__global__ __launch_bounds__(256) void k_gemv2(const float* __restrict__ W2,
                                               const float* __restrict__ gain2,
                                               float* __restrict__ out) {
    int row0 = blockIdx.x * RPB;
    float a0, a1, a2, a3;
    rows4_dot<HH>(W2, g_Ihid, row0, a0, a1, a2, a3);
    block_reduce4(a0, a1, a2, a3);
    __shared__ float cur[RPB];
    if (threadIdx.x == 0) {
        float g = gain2[0];
        float c0 = compress_fn(a0, g);
        float c1 = compress_fn(a1, g);
        float c2 = compress_fn(a2, g);
        float c3 = compress_fn(a3, g);
        g_Iout[row0 + 0] = c0;
        g_Iout[row0 + 1] = c1;
        g_Iout[row0 + 2] = c2;
        g_Iout[row0 + 3] = c3;
        cur[0] = c0; cur[1] = c1; cur[2] = c2; cur[3] = c3;
    }
    __syncthreads();
    if (threadIdx.x < RPB)
        izhi_run(HH + row0 + threadIdx.x, cur[threadIdx.x], out);
}

// GEMV 3: total_hidden = g_Ihid - Wfb @ g_Iout, then lanes 0-3 run the scan
// for the 4 hidden neurons. Extra block (blockIdx==2048) computes the loss
// (g_Iout was finalized by k_gemv2). Grid = HH/RPB + 1 = 2049.
__global__ __launch_bounds__(256) void k_gemv3(const float* __restrict__ Wfb,
                                               const float* __restrict__ target,
                                               float* __restrict__ out) {
    if (blockIdx.x == HH / RPB) {
        // loss = mean((I_output - target)^2)
        float acc = 0.0f;
        for (int i = threadIdx.x; i < ODIM; i += 256) {
            float d = g_Iout[i] - target[i];
            acc = fmaf(d, d, acc);
        }
        __shared__ float s[8];
        #pragma unroll
        for (int o = 16; o > 0; o >>= 1)
            acc += __shfl_xor_sync(0xffffffffu, acc, o);
        if ((threadIdx.x & 31) == 0) s[threadIdx.x >> 5] = acc;
        __syncthreads();
        if (threadIdx.x < 32) {
            acc = (threadIdx.x < 8) ? s[threadIdx.x] : 0.0f;
            #pragma unroll
            for (int o = 4; o > 0; o >>= 1)
                acc += __shfl_xor_sync(0xffffffffu, acc, o);
            if (threadIdx.x == 0)
                out[0] = acc / (float)ODIM;
        }
        return;
    }

    int row0 = blockIdx.x * RPB;
    float a0, a1, a2, a3;
    rows4_dot<ODIM>(Wfb, g_Iout, row0, a0, a1, a2, a3);
    block_reduce4(a0, a1, a2, a3);
    __shared__ float cur[RPB];
    if (threadIdx.x == 0) {
        cur[0] = g_Ihid[row0 + 0] - a0;
        cur[1] = g_Ihid[row0 + 1] - a1;
        cur[2] = g_Ihid[row0 + 2] - a2;
        cur[3] = g_Ihid[row0 + 3] - a3;
    }
    __syncthreads();
    if (threadIdx.x < RPB)
        izhi_run(row0 + threadIdx.x, cur[threadIdx.x], out);
}

extern "C" void kernel_launch(void* const* d_in, const int* in_sizes, int n_in,
                              void* d_out, int out_size) {
    // metadata order: v_input, target_output, W1, W2, W_feedback, gain1, gain2
    const float* v_input = (const float*)d_in[0];
    const float* target  = (const float*)d_in[1];
    const float* W1      = (const float*)d_in[2];
    const float* W2      = (const float*)d_in[3];
    const float* Wfb     = (const float*)d_in[4];
    const float* gain1   = (const float*)d_in[5];
    const float* gain2   = (const float*)d_in[6];
    float* out = (float*)d_out;

    k_gemv1<<<HH / RPB, 256>>>(W1, v_input, gain1);
    k_gemv2<<<ODIM / RPB, 256>>>(W2, gain2, out);
    k_gemv3<<<HH / RPB + 1, 256>>>(Wfb, target, out);
    (void)in_sizes; (void)n_in; (void)out_size;
}

// round 12
// speedup vs baseline: 1.0346x; 1.0064x over previous
#include <cuda_runtime.h>
#include <math.h>

// Problem constants
#define HH     8192
#define IDIM   4096
#define ODIM   4096
#define NTOT   (HH + ODIM)      // 12288
#define NSTEPS 100
#define RPB    4                // rows per group

// Scratch (no allocations allowed)
__device__ __align__(128) float g_Ihid[HH];      // compress(W1 @ v_input)
__device__ __align__(128) float g_Iout[ODIM];    // compress(W2 @ I_hidden)
__device__ __align__(128) float g_total_hid[HH]; // I_hidden - Wfb @ I_output

// Grid barrier state (sense-reversal; persists across graph replays safely:
// gen increments monotonically, count always returns to 0).
__device__ unsigned g_bar_cnt = 0;
__device__ volatile unsigned g_bar_gen = 0;

__device__ __forceinline__ void grid_barrier() {
    __syncthreads();
    if (threadIdx.x == 0) {
        unsigned gen = g_bar_gen;           // read phase BEFORE arriving
        __threadfence();                    // make this block's writes visible
        if (atomicAdd(&g_bar_cnt, 1u) == gridDim.x - 1u) {
            g_bar_cnt = 0;                  // reset before release
            __threadfence();
            g_bar_gen = gen + 1u;           // release (volatile store)
        } else {
            while (g_bar_gen == gen) { }    // spin on volatile
        }
    }
    __syncthreads();
}

__device__ __forceinline__ float compress_fn(float x, float gain) {
    float s = (x > 0.0f) ? 1.0f : ((x < 0.0f) ? -1.0f : 0.0f);
    return s * log1pf(gain * fabsf(x) + 1e-6f);
}

// 4-row dot: 256 threads, thread t handles idx = k*256+t, elements .x.y.z.w.
// Per-row FMA ordering identical to the passing kernels.
template <int NCOLS>
__device__ __forceinline__ void rows4_dot(const float* __restrict__ W,
                                          const float* __restrict__ x,
                                          int row0,
                                          float& a0, float& a1, float& a2, float& a3) {
    const float4* xv = reinterpret_cast<const float4*>(x);
    const float4* w0 = reinterpret_cast<const float4*>(W + (size_t)(row0 + 0) * NCOLS);
    const float4* w1 = reinterpret_cast<const float4*>(W + (size_t)(row0 + 1) * NCOLS);
    const float4* w2 = reinterpret_cast<const float4*>(W + (size_t)(row0 + 2) * NCOLS);
    const float4* w3 = reinterpret_cast<const float4*>(W + (size_t)(row0 + 3) * NCOLS);
    constexpr int PER = NCOLS / 4 / 256;
    a0 = a1 = a2 = a3 = 0.0f;
    #pragma unroll
    for (int k = 0; k < PER; ++k) {
        int idx = k * 256 + threadIdx.x;
        float4 xx = xv[idx];
        float4 r0 = w0[idx];
        float4 r1 = w1[idx];
        float4 r2 = w2[idx];
        float4 r3 = w3[idx];
        a0 = fmaf(r0.x, xx.x, a0); a0 = fmaf(r0.y, xx.y, a0);
        a0 = fmaf(r0.z, xx.z, a0); a0 = fmaf(r0.w, xx.w, a0);
        a1 = fmaf(r1.x, xx.x, a1); a1 = fmaf(r1.y, xx.y, a1);
        a1 = fmaf(r1.z, xx.z, a1); a1 = fmaf(r1.w, xx.w, a1);
        a2 = fmaf(r2.x, xx.x, a2); a2 = fmaf(r2.y, xx.y, a2);
        a2 = fmaf(r2.z, xx.z, a2); a2 = fmaf(r2.w, xx.w, a2);
        a3 = fmaf(r3.x, xx.x, a3); a3 = fmaf(r3.y, xx.y, a3);
        a3 = fmaf(r3.z, xx.z, a3); a3 = fmaf(r3.w, xx.w, a3);
    }
}

// Block reduce of 4 sums, 256 threads. Same xor tree as passing kernel.
// Entry __syncthreads makes it safe inside a loop (smem reuse).
__device__ __forceinline__ void block_reduce4(float& a0, float& a1, float& a2, float& a3) {
    __shared__ float s[8][4];
    __syncthreads();
    #pragma unroll
    for (int o = 16; o > 0; o >>= 1) {
        a0 += __shfl_xor_sync(0xffffffffu, a0, o);
        a1 += __shfl_xor_sync(0xffffffffu, a1, o);
        a2 += __shfl_xor_sync(0xffffffffu, a2, o);
        a3 += __shfl_xor_sync(0xffffffffu, a3, o);
    }
    if ((threadIdx.x & 31) == 0) {
        int w = threadIdx.x >> 5;
        s[w][0] = a0; s[w][1] = a1; s[w][2] = a2; s[w][3] = a3;
    }
    __syncthreads();
    if (threadIdx.x < 32) {
        bool in = threadIdx.x < 8;
        a0 = in ? s[threadIdx.x][0] : 0.0f;
        a1 = in ? s[threadIdx.x][1] : 0.0f;
        a2 = in ? s[threadIdx.x][2] : 0.0f;
        a3 = in ? s[threadIdx.x][3] : 0.0f;
        #pragma unroll
        for (int o = 4; o > 0; o >>= 1) {
            a0 += __shfl_xor_sync(0xffffffffu, a0, o);
            a1 += __shfl_xor_sync(0xffffffffu, a1, o);
            a2 += __shfl_xor_sync(0xffffffffu, a2, o);
            a3 += __shfl_xor_sync(0xffffffffu, a3, o);
        }
    }
}

// 100-step Izhikevich trajectory for one neuron. Lanes of a warp handle 32
// consecutive neurons -> 128B coalesced stores each step.
// Output layout: out[0]=loss, v at out[1 + t*NTOT + n], u after all v.
__device__ __forceinline__ void izhi_run(int n, float Iin, float* __restrict__ out) {
    float* vp = out + 1 + n;
    float* up = out + 1 + (size_t)NSTEPS * NTOT + n;
    float v = -65.0f;
    float u = 0.2f * -65.0f;   // -13
    *vp = v; *up = u;
    #pragma unroll 4
    for (int t = 1; t < NSTEPS; ++t) {
        vp += NTOT; up += NTOT;
        float vn = v + (0.04f * v * v + 5.0f * v + 0.14f - u + Iin);
        float un = u + 0.02f * (0.2f * v - u);
        bool sp = (vn >= 30.0f);
        v = sp ? -65.0f : vn;
        u = sp ? (un + 8.0f) : un;
        *vp = v; *up = u;
    }
}

// One persistent kernel. Grid = SMs * occupancy (all blocks co-resident).
__global__ __launch_bounds__(256) void k_fused(
    const float* __restrict__ vin,   const float* __restrict__ target,
    const float* __restrict__ W1,    const float* __restrict__ W2,
    const float* __restrict__ Wfb,   const float* __restrict__ gain1,
    const float* __restrict__ gain2, float* __restrict__ out)
{
    // ---- Phase 1: g_Ihid = compress(W1 @ v_input, gain1) ----
    for (int g = blockIdx.x; g < HH / RPB; g += gridDim.x) {
        int row0 = g * RPB;
        float a0, a1, a2, a3;
        rows4_dot<IDIM>(W1, vin, row0, a0, a1, a2, a3);
        block_reduce4(a0, a1, a2, a3);
        if (threadIdx.x == 0) {
            float gn = gain1[0];
            g_Ihid[row0 + 0] = compress_fn(a0, gn);
            g_Ihid[row0 + 1] = compress_fn(a1, gn);
            g_Ihid[row0 + 2] = compress_fn(a2, gn);
            g_Ihid[row0 + 3] = compress_fn(a3, gn);
        }
    }
    grid_barrier();

    // ---- Phase 2: g_Iout = compress(W2 @ g_Ihid, gain2) ----
    for (int g = blockIdx.x; g < ODIM / RPB; g += gridDim.x) {
        int row0 = g * RPB;
        float a0, a1, a2, a3;
        rows4_dot<HH>(W2, g_Ihid, row0, a0, a1, a2, a3);
        block_reduce4(a0, a1, a2, a3);
        if (threadIdx.x == 0) {
            float gn = gain2[0];
            g_Iout[row0 + 0] = compress_fn(a0, gn);
            g_Iout[row0 + 1] = compress_fn(a1, gn);
            g_Iout[row0 + 2] = compress_fn(a2, gn);
            g_Iout[row0 + 3] = compress_fn(a3, gn);
        }
    }
    grid_barrier();

    // ---- Phase 3: Wfb streaming + loss + output-neuron izhi (interleaved,
    //      the latter two hide under the DRAM stream) ----
    const int NG_W    = HH / RPB;          // 2048 Wfb row-groups
    const int NG_LOSS = NG_W;              // 1 loss group
    const int NG_OIZ0 = NG_W + 1;          // first output-izhi group
    const int NG3     = NG_OIZ0 + ODIM / 32;  // + 128 izhi groups
    for (int g = blockIdx.x; g < NG3; g += gridDim.x) {
        if (g < NG_W) {
            int row0 = g * RPB;
            float a0, a1, a2, a3;
            rows4_dot<ODIM>(Wfb, g_Iout, row0, a0, a1, a2, a3);
            block_reduce4(a0, a1, a2, a3);
            if (threadIdx.x == 0) {
                g_total_hid[row0 + 0] = g_Ihid[row0 + 0] - a0;
                g_total_hid[row0 + 1] = g_Ihid[row0 + 1] - a1;
                g_total_hid[row0 + 2] = g_Ihid[row0 + 2] - a2;
                g_total_hid[row0 + 3] = g_Ihid[row0 + 3] - a3;
            }
        } else if (g == NG_LOSS) {
            // loss = mean((I_output - target)^2)
            float acc = 0.0f;
            for (int i = threadIdx.x; i < ODIM; i += 256) {
                float d = g_Iout[i] - target[i];
                acc = fmaf(d, d, acc);
            }
            __shared__ float ls[8];
            #pragma unroll
            for (int o = 16; o > 0; o >>= 1)
                acc += __shfl_xor_sync(0xffffffffu, acc, o);
            if ((threadIdx.x & 31) == 0) ls[threadIdx.x >> 5] = acc;
            __syncthreads();
            if (threadIdx.x < 32) {
                acc = (threadIdx.x < 8) ? ls[threadIdx.x] : 0.0f;
                #pragma unroll
                for (int o = 4; o > 0; o >>= 1)
                    acc += __shfl_xor_sync(0xffffffffu, acc, o);
                if (threadIdx.x == 0)
                    out[0] = acc / (float)ODIM;
            }
            __syncthreads();
        } else {
            int og = g - NG_OIZ0;           // 0..127, 32 neurons each
            if (threadIdx.x < 32) {
                int n = og * 32 + threadIdx.x;
                izhi_run(HH + n, g_Iout[n], out);
            }
        }
    }
    grid_barrier();

    // ---- Phase 4: hidden-neuron izhi, 32 neurons/block spread across SMs ----
    for (int g = blockIdx.x; g < HH / 32; g += gridDim.x) {
        if (threadIdx.x < 32) {
            int n = g * 32 + threadIdx.x;
            izhi_run(n, g_total_hid[n], out);
        }
    }
}

extern "C" void kernel_launch(void* const* d_in, const int* in_sizes, int n_in,
                              void* d_out, int out_size) {
    // metadata order: v_input, target_output, W1, W2, W_feedback, gain1, gain2
    const float* v_input = (const float*)d_in[0];
    const float* target  = (const float*)d_in[1];
    const float* W1      = (const float*)d_in[2];
    const float* W2      = (const float*)d_in[3];
    const float* Wfb     = (const float*)d_in[4];
    const float* gain1   = (const float*)d_in[5];
    const float* gain2   = (const float*)d_in[6];
    float* out = (float*)d_out;

    // Grid sized to guaranteed co-residency (spin barrier is deadlock-free).
    int dev = 0;
    cudaGetDevice(&dev);
    int sm = 0;
    cudaDeviceGetAttribute(&sm, cudaDevAttrMultiProcessorCount, dev);
    int occ = 0;
    cudaOccupancyMaxActiveBlocksPerMultiprocessor(&occ, k_fused, 256, 0);
    if (occ < 1) occ = 1;
    if (sm < 1) sm = 1;
    int grid = sm * occ;

    k_fused<<<grid, 256>>>(v_input, target, W1, W2, Wfb, gain1, gain2, out);
    (void)in_sizes; (void)n_in; (void)out_size;
}